// round 2
// baseline (speedup 1.0000x reference)
#include <cuda_runtime.h>

#define BATCH 256
#define SEQ   128
#define EDIM  512
#define HD    256
#define G4    1024
#define NTAG  76
#define MROWS 32768   // SEQ*BATCH

// ---------------- scratch (device globals; no runtime allocation) ----------------
__device__ float d_Zf[(size_t)MROWS * G4];   // input proj fwd, (S,B,4HD), gate order i,f,g,o
__device__ float d_Zb[(size_t)MROWS * G4];   // input proj bwd
__device__ float d_HF[(size_t)MROWS * HD];   // fwd hidden history (S,B,HD)
__device__ float d_HB[(size_t)MROWS * HD];   // bwd hidden history (S,B,HD)
__device__ float d_Hping[2 * 2 * BATCH * HD]; // [parity][dir][b][hu]
__device__ float d_C[2 * BATCH * HD];         // [dir][b][hu]
__device__ float d_em[(size_t)MROWS * NTAG];  // emissions (S,B,T)
__device__ float d_llh[BATCH];

__device__ __forceinline__ float sigm(float x)  { return 1.0f / (1.0f + __expf(-x)); }
__device__ __forceinline__ float tanh_(float x) { float e = __expf(2.0f * x); return 1.0f - 2.0f / (e + 1.0f); }

// ---------------- init: h0 -> ping buffer parity 0, c0 -> cell state ----------------
__global__ void k_init(const float* __restrict__ h0, const float* __restrict__ c0)
{
    int i = blockIdx.x * 256 + threadIdx.x;   // grid 512 -> 131072 exact
    d_Hping[i] = h0[i];
    d_C[i]     = c0[i];
}

// ---------------- Z = embed[ids] @ [Wf;Wb]^T + (b_ih+b_hh) ----------------
// M=32768 (r = s*B + b), N=2048 (cols 0..1023 fwd | 1024..2047 bwd), K=512
// BM=128, BN=128, BK=8, 256 threads, 8x8 microtile.
__global__ void __launch_bounds__(256) k_input_gemm(
    const int*   __restrict__ ids,  const float* __restrict__ embed,
    const float* __restrict__ Wf,   const float* __restrict__ Wb,
    const float* __restrict__ bihf, const float* __restrict__ bhhf,
    const float* __restrict__ bihb, const float* __restrict__ bhhb)
{
    __shared__ float As[8][128];
    __shared__ float Bs[8][128];
    __shared__ int   sIds[128];

    int tid = threadIdx.x;
    int bx = blockIdx.x;   // N tile 0..15
    int by = blockIdx.y;   // M tile 0..255

    if (tid < 128) {
        int r = by * 128 + tid;                       // r = s*256 + b
        sIds[tid] = ids[(r & 255) * SEQ + (r >> 8)];  // input_ids[b*S + s]
    }
    __syncthreads();

    int tx = tid & 15, ty = tid >> 4;
    float acc[8][8];
    #pragma unroll
    for (int i = 0; i < 8; i++)
        #pragma unroll
        for (int j = 0; j < 8; j++) acc[i][j] = 0.f;

    int jn0 = bx * 128;
    const float* W   = (jn0 < 1024) ? Wf : Wb;
    int joff         = (jn0 < 1024) ? jn0 : jn0 - 1024;

    int arow = tid >> 1, ak = (tid & 1) * 4;

    for (int k0 = 0; k0 < EDIM; k0 += 8) {
        float4 av = *(const float4*)(embed + (size_t)sIds[arow] * EDIM + k0 + ak);
        float4 bv = *(const float4*)(W + (size_t)(joff + arow) * EDIM + k0 + ak);
        As[ak+0][arow] = av.x; As[ak+1][arow] = av.y; As[ak+2][arow] = av.z; As[ak+3][arow] = av.w;
        Bs[ak+0][arow] = bv.x; Bs[ak+1][arow] = bv.y; Bs[ak+2][arow] = bv.z; Bs[ak+3][arow] = bv.w;
        __syncthreads();
        #pragma unroll
        for (int k = 0; k < 8; k++) {
            float4 a0 = *(const float4*)&As[k][ty*8];
            float4 a1 = *(const float4*)&As[k][ty*8+4];
            float4 b0 = *(const float4*)&Bs[k][tx*8];
            float4 b1 = *(const float4*)&Bs[k][tx*8+4];
            float a[8] = {a0.x,a0.y,a0.z,a0.w,a1.x,a1.y,a1.z,a1.w};
            float b[8] = {b0.x,b0.y,b0.z,b0.w,b1.x,b1.y,b1.z,b1.w};
            #pragma unroll
            for (int i = 0; i < 8; i++)
                #pragma unroll
                for (int j = 0; j < 8; j++) acc[i][j] = fmaf(a[i], b[j], acc[i][j]);
        }
        __syncthreads();
    }

    float* Z        = (jn0 < 1024) ? d_Zf : d_Zb;
    const float* bi = (jn0 < 1024) ? bihf : bihb;
    const float* bh = (jn0 < 1024) ? bhhf : bhhb;
    #pragma unroll
    for (int i = 0; i < 8; i++) {
        int r = by * 128 + ty * 8 + i;
        #pragma unroll
        for (int j = 0; j < 8; j++) {
            int jc = joff + tx * 8 + j;
            Z[(size_t)r * G4 + jc] = acc[i][j] + bi[jc] + bh[jc];
        }
    }
}

// ---------------- one LSTM time step, both directions, gates fused ----------------
// grid (16 hu-tiles, 4 b-tiles, 2 dirs) = 128 blocks. Block: 64 b x (16 hu x 4 gates), K=256.
__global__ void __launch_bounds__(256) k_step(
    int t, const float* __restrict__ Whf, const float* __restrict__ Whb)
{
    __shared__ float Hs[16][64];        // [k][b_local]
    __shared__ float Ws2[16][16][4];    // [k][hu_local][gate]

    int dir = blockIdx.z;
    int hu0 = blockIdx.x * 16;
    int b0  = blockIdx.y * 64;
    int s   = dir ? (SEQ - 1 - t) : t;

    const float* Whh   = dir ? Whb : Whf;
    const float* hprev = d_Hping + (size_t)(t & 1) * 131072 + (size_t)dir * 65536;
    float*       hnext = d_Hping + (size_t)((t + 1) & 1) * 131072 + (size_t)dir * 65536;
    const float* Z     = dir ? d_Zb : d_Zf;
    float*       Hist  = dir ? d_HB : d_HF;

    int tid = threadIdx.x;
    int tx = tid & 15, ty = tid >> 4;   // tx: hu_local, ty: b group (4 rows)

    float acc[4][4];   // [bi][gate]
    #pragma unroll
    for (int i = 0; i < 4; i++)
        #pragma unroll
        for (int g = 0; g < 4; g++) acc[i][g] = 0.f;

    int lr = tid >> 2, lk = (tid & 3) * 4;              // Hs load: b row, k quad
    int wg = tid >> 6, whu = (tid >> 2) & 15, wk = (tid & 3) * 4;  // Ws load

    for (int k0 = 0; k0 < HD; k0 += 16) {
        float4 hv = *(const float4*)(hprev + (size_t)(b0 + lr) * HD + k0 + lk);
        Hs[lk+0][lr] = hv.x; Hs[lk+1][lr] = hv.y; Hs[lk+2][lr] = hv.z; Hs[lk+3][lr] = hv.w;
        float4 wv = *(const float4*)(Whh + (size_t)(wg * 256 + hu0 + whu) * HD + k0 + wk);
        Ws2[wk+0][whu][wg] = wv.x; Ws2[wk+1][whu][wg] = wv.y;
        Ws2[wk+2][whu][wg] = wv.z; Ws2[wk+3][whu][wg] = wv.w;
        __syncthreads();
        #pragma unroll
        for (int k = 0; k < 16; k++) {
            float4 h4 = *(const float4*)&Hs[k][ty * 4];
            float hvals[4] = {h4.x, h4.y, h4.z, h4.w};
            float4 w4 = *(const float4*)&Ws2[k][tx][0];
            float wv4[4] = {w4.x, w4.y, w4.z, w4.w};
            #pragma unroll
            for (int i = 0; i < 4; i++)
                #pragma unroll
                for (int g = 0; g < 4; g++) acc[i][g] = fmaf(hvals[i], wv4[g], acc[i][g]);
        }
        __syncthreads();
    }

    int hu = hu0 + tx;
    #pragma unroll
    for (int i = 0; i < 4; i++) {
        int b = b0 + ty * 4 + i;
        size_t zrow = (size_t)(s * BATCH + b) * G4;
        float zi = Z[zrow + 0 * HD + hu] + acc[i][0];
        float zf = Z[zrow + 1 * HD + hu] + acc[i][1];
        float zg = Z[zrow + 2 * HD + hu] + acc[i][2];
        float zo = Z[zrow + 3 * HD + hu] + acc[i][3];
        size_t ci = (size_t)dir * 65536 + (size_t)b * HD + hu;
        float c = sigm(zf) * d_C[ci] + sigm(zi) * tanh_(zg);
        float h = sigm(zo) * tanh_(c);
        d_C[ci] = c;
        hnext[(size_t)b * HD + hu] = h;
        Hist[(size_t)(s * BATCH + b) * HD + hu] = h;
    }
}

// ---------------- em = [HF|HB] @ W_out^T + b_out ----------------
// grid 512 blocks: 64 rows x 80 cols (76 used), K=512, BK=16
__global__ void __launch_bounds__(256) k_emis(
    const float* __restrict__ Wout, const float* __restrict__ bout)
{
    __shared__ float As[16][64];   // [k][row]
    __shared__ float Bs[16][80];   // [k][col]
    int tid = threadIdx.x;
    int r0 = blockIdx.x * 64;
    int tx = tid & 15, ty = tid >> 4;   // tx: 5 cols, ty: 4 rows
    float acc[4][5];
    #pragma unroll
    for (int i = 0; i < 4; i++)
        #pragma unroll
        for (int j = 0; j < 5; j++) acc[i][j] = 0.f;

    int lr = tid >> 2, lk = (tid & 3) * 4;
    for (int k0 = 0; k0 < 512; k0 += 16) {
        const float* Abase = (k0 < 256)
            ? (d_HF + (size_t)(r0 + lr) * HD + k0)
            : (d_HB + (size_t)(r0 + lr) * HD + (k0 - 256));
        float4 av = *(const float4*)(Abase + lk);
        As[lk+0][lr] = av.x; As[lk+1][lr] = av.y; As[lk+2][lr] = av.z; As[lk+3][lr] = av.w;
        for (int idx = tid; idx < 80 * 16; idx += 256) {
            int j = idx >> 4, k = idx & 15;
            Bs[k][j] = (j < NTAG) ? Wout[(size_t)j * 512 + k0 + k] : 0.f;
        }
        __syncthreads();
        #pragma unroll
        for (int k = 0; k < 16; k++) {
            float4 a4 = *(const float4*)&As[k][ty * 4];
            float a[4] = {a4.x, a4.y, a4.z, a4.w};
            float bvals[5];
            #pragma unroll
            for (int j = 0; j < 5; j++) bvals[j] = Bs[k][tx * 5 + j];
            #pragma unroll
            for (int i = 0; i < 4; i++)
                #pragma unroll
                for (int j = 0; j < 5; j++) acc[i][j] = fmaf(a[i], bvals[j], acc[i][j]);
        }
        __syncthreads();
    }
    #pragma unroll
    for (int i = 0; i < 4; i++) {
        int r = r0 + ty * 4 + i;
        #pragma unroll
        for (int j = 0; j < 5; j++) {
            int c = tx * 5 + j;
            if (c < NTAG) d_em[(size_t)r * NTAG + c] = acc[i][j] + bout[c];
        }
    }
}

// ---------------- CRF: one block per batch element ----------------
__global__ void __launch_bounds__(128) k_crf(
    const int* __restrict__ tag_ids, const int* __restrict__ lengths,
    const float* __restrict__ start, const float* __restrict__ endt,
    const float* __restrict__ trans)
{
    __shared__ float E[NTAG * NTAG];
    __shared__ float alpha[128];
    __shared__ float p[128];
    __shared__ float red[128];
    int b = blockIdx.x;
    int tid = threadIdx.x;
    int len = lengths[b];

    for (int i = tid; i < NTAG * NTAG; i += 128) E[i] = __expf(trans[i]);

    alpha[tid] = (tid < NTAG) ? start[tid] + d_em[(size_t)b * NTAG + tid] : -1e30f;

    // gold-path score, serial (no syncs inside)
    float score = 0.f;
    if (tid == 0) {
        int prev = tag_ids[b * SEQ + 0];
        score = start[prev] + d_em[(size_t)b * NTAG + prev];
        for (int t = 1; t < len; t++) {
            int tg = tag_ids[b * SEQ + t];
            score += trans[prev * NTAG + tg] + d_em[(size_t)(t * BATCH + b) * NTAG + tg];
            prev = tg;
        }
        score += endt[prev];
    }
    __syncthreads();

    for (int t = 1; t < len; t++) {
        red[tid] = alpha[tid];
        __syncthreads();
        for (int s = 64; s > 0; s >>= 1) {
            if (tid < s) red[tid] = fmaxf(red[tid], red[tid + s]);
            __syncthreads();
        }
        float m = red[0];
        p[tid] = (tid < NTAG) ? __expf(alpha[tid] - m) : 0.f;
        __syncthreads();
        if (tid < NTAG) {
            float sum = 0.f;
            #pragma unroll 4
            for (int i = 0; i < NTAG; i++) sum = fmaf(p[i], E[i * NTAG + tid], sum);
            alpha[tid] = m + __logf(sum) + d_em[(size_t)(t * BATCH + b) * NTAG + tid];
        }
        __syncthreads();
    }

    // logZ = logsumexp(alpha + end)
    red[tid] = (tid < NTAG) ? alpha[tid] + endt[tid] : -1e30f;
    __syncthreads();
    for (int s = 64; s > 0; s >>= 1) {
        if (tid < s) red[tid] = fmaxf(red[tid], red[tid + s]);
        __syncthreads();
    }
    float m = red[0];
    __syncthreads();
    red[tid] = (tid < NTAG) ? __expf(alpha[tid] + endt[tid] - m) : 0.f;
    __syncthreads();
    for (int s = 64; s > 0; s >>= 1) {
        if (tid < s) red[tid] += red[tid + s];
        __syncthreads();
    }
    if (tid == 0) d_llh[b] = score - (m + __logf(red[0]));
}

// ---------------- final reduce: out = -mean(llh) ----------------
__global__ void k_reduce(float* __restrict__ out)
{
    __shared__ float red[256];
    int tid = threadIdx.x;
    red[tid] = d_llh[tid];
    __syncthreads();
    for (int s = 128; s > 0; s >>= 1) {
        if (tid < s) red[tid] += red[tid + s];
        __syncthreads();
    }
    if (tid == 0) out[0] = -red[0] / 256.f;
}

extern "C" void kernel_launch(void* const* d_in, const int* in_sizes, int n_in,
                              void* d_out, int out_size)
{
    const int*   ids   = (const int*)d_in[0];
    const int*   tags  = (const int*)d_in[1];
    const int*   lens  = (const int*)d_in[2];
    const float* embed = (const float*)d_in[3];
    const float* Wihf  = (const float*)d_in[4];
    const float* Whhf  = (const float*)d_in[5];
    const float* bihf  = (const float*)d_in[6];
    const float* bhhf  = (const float*)d_in[7];
    const float* Wihb  = (const float*)d_in[8];
    const float* Whhb  = (const float*)d_in[9];
    const float* bihb  = (const float*)d_in[10];
    const float* bhhb  = (const float*)d_in[11];
    const float* Wout  = (const float*)d_in[12];
    const float* bout  = (const float*)d_in[13];
    const float* start = (const float*)d_in[14];
    const float* endt  = (const float*)d_in[15];
    const float* trans = (const float*)d_in[16];
    const float* h0    = (const float*)d_in[17];
    const float* c0    = (const float*)d_in[18];
    float* out = (float*)d_out;

    k_init<<<512, 256>>>(h0, c0);
    k_input_gemm<<<dim3(16, 256), 256>>>(ids, embed, Wihf, Wihb, bihf, bhhf, bihb, bhhb);
    for (int t = 0; t < SEQ; t++)
        k_step<<<dim3(16, 4, 2), 256>>>(t, Whhf, Whhb);
    k_emis<<<512, 256>>>(Wout, bout);
    k_crf<<<256, 128>>>(tags, lens, start, endt, trans);
    k_reduce<<<1, 256>>>(out);
}

// round 3
// speedup vs baseline: 1.2589x; 1.2589x over previous
#include <cuda_runtime.h>

#define BATCH 256
#define SEQ   128
#define EDIM  512
#define HD    256
#define G4    1024
#define NTAG  76
#define MROWS 32768   // SEQ*BATCH
#define RB    128     // resident blocks in persistent recurrence

// ---------------- scratch (device globals; no runtime allocation) ----------------
__device__ float d_Zf[(size_t)MROWS * G4];   // input proj fwd, (S,B,4HD), gate order i,f,g,o
__device__ float d_Zb[(size_t)MROWS * G4];   // input proj bwd
__device__ float d_HF[(size_t)MROWS * HD];   // fwd hidden history (S,B,HD)
__device__ float d_HB[(size_t)MROWS * HD];   // bwd hidden history (S,B,HD)
__device__ float d_Hping[2 * 2 * BATCH * HD]; // [parity][dir][b][hu]
__device__ float d_C[2 * BATCH * HD];         // [dir][b][hu]
__device__ float d_em[(size_t)MROWS * NTAG];  // emissions (S,B,T)
__device__ float d_llh[BATCH];

__device__ unsigned          d_barCount;
__device__ volatile unsigned d_barPhase;

__device__ __forceinline__ float sigm(float x)  { return 1.0f / (1.0f + __expf(-x)); }
__device__ __forceinline__ float tanh_(float x) { float e = __expf(2.0f * x); return 1.0f - 2.0f / (e + 1.0f); }

// ---------------- init: h0 -> ping parity 0, c0 -> cell state, reset barrier ----------------
__global__ void k_init(const float* __restrict__ h0, const float* __restrict__ c0)
{
    int i = blockIdx.x * 256 + threadIdx.x;   // grid 512 -> 131072 exact
    d_Hping[i] = h0[i];
    d_C[i]     = c0[i];
    if (i == 0) { d_barCount = 0; d_barPhase = 0; }
}

// ---------------- Z = embed[ids] @ [Wf;Wb]^T + (b_ih+b_hh) ----------------
// M=32768 (r = s*B + b), N=2048 (cols 0..1023 fwd | 1024..2047 bwd), K=512
// BM=128, BN=128, BK=8, 256 threads, 8x8 microtile, reg-prefetch pipeline.
__global__ void __launch_bounds__(256) k_input_gemm(
    const int*   __restrict__ ids,  const float* __restrict__ embed,
    const float* __restrict__ Wf,   const float* __restrict__ Wb,
    const float* __restrict__ bihf, const float* __restrict__ bhhf,
    const float* __restrict__ bihb, const float* __restrict__ bhhb)
{
    __shared__ float As[8][128];
    __shared__ float Bs[8][128];
    __shared__ int   sIds[128];

    int tid = threadIdx.x;
    int bx = blockIdx.x;   // N tile 0..15
    int by = blockIdx.y;   // M tile 0..255

    if (tid < 128) {
        int r = by * 128 + tid;                       // r = s*256 + b
        sIds[tid] = ids[(r & 255) * SEQ + (r >> 8)];  // input_ids[b*S + s]
    }
    __syncthreads();

    int tx = tid & 15, ty = tid >> 4;
    float acc[8][8];
    #pragma unroll
    for (int i = 0; i < 8; i++)
        #pragma unroll
        for (int j = 0; j < 8; j++) acc[i][j] = 0.f;

    int jn0 = bx * 128;
    const float* W   = (jn0 < 1024) ? Wf : Wb;
    int joff         = (jn0 < 1024) ? jn0 : jn0 - 1024;

    int arow = tid >> 1, ak = (tid & 1) * 4;
    const float* Arow = embed + (size_t)sIds[arow] * EDIM;
    const float* Brow = W + (size_t)(joff + arow) * EDIM;

    float4 av = *(const float4*)(Arow + ak);
    float4 bv = *(const float4*)(Brow + ak);

    for (int k0 = 0; k0 < EDIM; k0 += 8) {
        As[ak+0][arow] = av.x; As[ak+1][arow] = av.y; As[ak+2][arow] = av.z; As[ak+3][arow] = av.w;
        Bs[ak+0][arow] = bv.x; Bs[ak+1][arow] = bv.y; Bs[ak+2][arow] = bv.z; Bs[ak+3][arow] = bv.w;
        __syncthreads();
        if (k0 + 8 < EDIM) {
            av = *(const float4*)(Arow + k0 + 8 + ak);
            bv = *(const float4*)(Brow + k0 + 8 + ak);
        }
        #pragma unroll
        for (int k = 0; k < 8; k++) {
            float4 a0 = *(const float4*)&As[k][ty*8];
            float4 a1 = *(const float4*)&As[k][ty*8+4];
            float4 b0 = *(const float4*)&Bs[k][tx*8];
            float4 b1 = *(const float4*)&Bs[k][tx*8+4];
            float a[8] = {a0.x,a0.y,a0.z,a0.w,a1.x,a1.y,a1.z,a1.w};
            float b[8] = {b0.x,b0.y,b0.z,b0.w,b1.x,b1.y,b1.z,b1.w};
            #pragma unroll
            for (int i = 0; i < 8; i++)
                #pragma unroll
                for (int j = 0; j < 8; j++) acc[i][j] = fmaf(a[i], b[j], acc[i][j]);
        }
        __syncthreads();
    }

    float* Z        = (jn0 < 1024) ? d_Zf : d_Zb;
    const float* bi = (jn0 < 1024) ? bihf : bihb;
    const float* bh = (jn0 < 1024) ? bhhf : bhhb;
    #pragma unroll
    for (int i = 0; i < 8; i++) {
        int r = by * 128 + ty * 8 + i;
        #pragma unroll
        for (int j = 0; j < 8; j++) {
            int jc = joff + tx * 8 + j;
            Z[(size_t)r * G4 + jc] = acc[i][j] + bi[jc] + bh[jc];
        }
    }
}

// ---------------- persistent recurrence: all 128 steps, both dirs, 1 launch ----------------
// 128 blocks x 256 threads. block = (dir, hu-tile of 16, b-tile of 64).
// Whh slice (4 gates x 16 hu x 256 K = 64KB) loaded to smem ONCE. Device-wide
// barrier (atomic count + phase) between steps. All 128 blocks co-resident (<=148 SMs).
extern __shared__ float smem_dyn[];

__device__ __forceinline__ void grid_barrier(unsigned target)
{
    __syncthreads();
    if (threadIdx.x == 0) {
        __threadfence();
        unsigned arrived = atomicAdd(&d_barCount, 1u) + 1;
        if (arrived == target * RB) {
            __threadfence();
            d_barPhase = target;
        } else {
            while (d_barPhase < target) __nanosleep(64);
            __threadfence();
        }
    }
    __syncthreads();
}

__global__ void __launch_bounds__(256, 1) k_recurrent(
    const float* __restrict__ Whf, const float* __restrict__ Whb)
{
    float* Ws = smem_dyn;            // [256 k][16 hu][4 g] = 16384 floats
    float* Hs = smem_dyn + 16384;    // [32 k][64 b] = 2048 floats

    int bid = blockIdx.x;
    int dir = bid >> 6;
    int hu0 = ((bid >> 2) & 15) * 16;
    int b0  = (bid & 3) * 64;
    int tid = threadIdx.x;

    const float* Whh = dir ? Whb : Whf;
    const float* Z   = dir ? d_Zb : d_Zf;
    float* Hist      = dir ? d_HB : d_HF;
    float* Cc        = d_C + (size_t)dir * 65536;

    // ---- load W slice once: Ws[k][hu][g] = Whh[(g*256 + hu0+hu)*256 + k] ----
    {
        int pair = tid & 63;          // (hu,g)
        int hu = pair >> 2, g = pair & 3;
        int kq = tid >> 6;            // k quadrant of 64
        const float4* src = (const float4*)(Whh + (size_t)(g * 256 + hu0 + hu) * HD + kq * 64);
        #pragma unroll
        for (int i = 0; i < 16; i++) {
            float4 v = src[i];
            int k = kq * 64 + i * 4;
            Ws[(k+0)*64 + hu*4 + g] = v.x;
            Ws[(k+1)*64 + hu*4 + g] = v.y;
            Ws[(k+2)*64 + hu*4 + g] = v.z;
            Ws[(k+3)*64 + hu*4 + g] = v.w;
        }
    }

    int tx = tid & 15, ty = tid >> 4;   // tx: hu_local, ty: b group of 4
    int lrow = tid & 63;                // Hs loader: local b row
    int lkq  = tid >> 6;                // Hs loader: k quad

    for (int t = 0; t < SEQ; t++) {
        int s = dir ? (SEQ - 1 - t) : t;
        const float* hprev = d_Hping + (size_t)((t & 1) * 2 + dir) * 65536;
        float*       hnext = d_Hping + (size_t)(((t + 1) & 1) * 2 + dir) * 65536;

        // prefetch Z gate biases for this thread's outputs (independent of GEMM)
        float zv[4][4];
        #pragma unroll
        for (int i = 0; i < 4; i++) {
            int b = b0 + ty * 4 + i;
            const float* zr = Z + (size_t)(s * BATCH + b) * G4 + hu0 + tx;
            zv[i][0] = zr[0];
            zv[i][1] = zr[HD];
            zv[i][2] = zr[2*HD];
            zv[i][3] = zr[3*HD];
        }

        float acc[4][4];
        #pragma unroll
        for (int i = 0; i < 4; i++)
            #pragma unroll
            for (int g = 0; g < 4; g++) acc[i][g] = 0.f;

        for (int k0 = 0; k0 < HD; k0 += 32) {
            float4 h0v = *(const float4*)(hprev + (size_t)(b0 + lrow) * HD + k0 + lkq * 4);
            float4 h1v = *(const float4*)(hprev + (size_t)(b0 + lrow) * HD + k0 + 16 + lkq * 4);
            __syncthreads();   // previous chunk's compute done
            Hs[(lkq*4+0)*64 + lrow] = h0v.x;
            Hs[(lkq*4+1)*64 + lrow] = h0v.y;
            Hs[(lkq*4+2)*64 + lrow] = h0v.z;
            Hs[(lkq*4+3)*64 + lrow] = h0v.w;
            Hs[(16+lkq*4+0)*64 + lrow] = h1v.x;
            Hs[(16+lkq*4+1)*64 + lrow] = h1v.y;
            Hs[(16+lkq*4+2)*64 + lrow] = h1v.z;
            Hs[(16+lkq*4+3)*64 + lrow] = h1v.w;
            __syncthreads();
            #pragma unroll
            for (int k = 0; k < 32; k++) {
                float4 h4 = *(const float4*)&Hs[k*64 + ty*4];
                float4 w4 = *(const float4*)&Ws[(k0+k)*64 + tx*4];
                float hv[4] = {h4.x, h4.y, h4.z, h4.w};
                float wv[4] = {w4.x, w4.y, w4.z, w4.w};
                #pragma unroll
                for (int i = 0; i < 4; i++)
                    #pragma unroll
                    for (int g = 0; g < 4; g++) acc[i][g] = fmaf(hv[i], wv[g], acc[i][g]);
            }
        }

        int hu = hu0 + tx;
        #pragma unroll
        for (int i = 0; i < 4; i++) {
            int b = b0 + ty * 4 + i;
            float zi = zv[i][0] + acc[i][0];
            float zf = zv[i][1] + acc[i][1];
            float zg = zv[i][2] + acc[i][2];
            float zo = zv[i][3] + acc[i][3];
            size_t ci = (size_t)b * HD + hu;
            float c = sigm(zf) * Cc[ci] + sigm(zi) * tanh_(zg);
            float h = sigm(zo) * tanh_(c);
            Cc[ci] = c;
            hnext[ci] = h;
            Hist[(size_t)(s * BATCH + b) * HD + hu] = h;
        }

        grid_barrier((unsigned)(t + 1));
    }
}

// ---------------- em = [HF|HB] @ W_out^T + b_out ----------------
__global__ void __launch_bounds__(256) k_emis(
    const float* __restrict__ Wout, const float* __restrict__ bout)
{
    __shared__ float As[16][64];   // [k][row]
    __shared__ float Bs[16][80];   // [k][col]
    int tid = threadIdx.x;
    int r0 = blockIdx.x * 64;
    int tx = tid & 15, ty = tid >> 4;   // tx: 5 cols, ty: 4 rows
    float acc[4][5];
    #pragma unroll
    for (int i = 0; i < 4; i++)
        #pragma unroll
        for (int j = 0; j < 5; j++) acc[i][j] = 0.f;

    int lr = tid >> 2, lk = (tid & 3) * 4;
    for (int k0 = 0; k0 < 512; k0 += 16) {
        const float* Abase = (k0 < 256)
            ? (d_HF + (size_t)(r0 + lr) * HD + k0)
            : (d_HB + (size_t)(r0 + lr) * HD + (k0 - 256));
        float4 av = *(const float4*)(Abase + lk);
        As[lk+0][lr] = av.x; As[lk+1][lr] = av.y; As[lk+2][lr] = av.z; As[lk+3][lr] = av.w;
        for (int idx = tid; idx < 80 * 16; idx += 256) {
            int j = idx >> 4, k = idx & 15;
            Bs[k][j] = (j < NTAG) ? Wout[(size_t)j * 512 + k0 + k] : 0.f;
        }
        __syncthreads();
        #pragma unroll
        for (int k = 0; k < 16; k++) {
            float4 a4 = *(const float4*)&As[k][ty * 4];
            float a[4] = {a4.x, a4.y, a4.z, a4.w};
            float bvals[5];
            #pragma unroll
            for (int j = 0; j < 5; j++) bvals[j] = Bs[k][tx * 5 + j];
            #pragma unroll
            for (int i = 0; i < 4; i++)
                #pragma unroll
                for (int j = 0; j < 5; j++) acc[i][j] = fmaf(a[i], bvals[j], acc[i][j]);
        }
        __syncthreads();
    }
    #pragma unroll
    for (int i = 0; i < 4; i++) {
        int r = r0 + ty * 4 + i;
        #pragma unroll
        for (int j = 0; j < 5; j++) {
            int c = tx * 5 + j;
            if (c < NTAG) d_em[(size_t)r * NTAG + c] = acc[i][j] + bout[c];
        }
    }
}

// ---------------- CRF: one block per batch element ----------------
__global__ void __launch_bounds__(128) k_crf(
    const int* __restrict__ tag_ids, const int* __restrict__ lengths,
    const float* __restrict__ start, const float* __restrict__ endt,
    const float* __restrict__ trans)
{
    __shared__ float E[NTAG * NTAG];
    __shared__ float alpha[128];
    __shared__ float p[128];
    __shared__ float red[128];
    int b = blockIdx.x;
    int tid = threadIdx.x;
    int len = lengths[b];

    for (int i = tid; i < NTAG * NTAG; i += 128) E[i] = __expf(trans[i]);

    // ---- gold-path score: parallel over t ----
    float part = 0.f;
    if (tid >= 1 && tid < len) {
        int tg = tag_ids[b * SEQ + tid];
        int pv = tag_ids[b * SEQ + tid - 1];
        part = trans[pv * NTAG + tg] + d_em[(size_t)(tid * BATCH + b) * NTAG + tg];
    }
    if (tid == 0) {
        int t0 = tag_ids[b * SEQ];
        part += start[t0] + d_em[(size_t)b * NTAG + t0];
        part += endt[tag_ids[b * SEQ + len - 1]];
    }
    red[tid] = part;
    alpha[tid] = (tid < NTAG) ? start[tid] + d_em[(size_t)b * NTAG + tid] : 0.f;
    __syncthreads();
    for (int s2 = 64; s2 > 0; s2 >>= 1) {
        if (tid < s2) red[tid] += red[tid + s2];
        __syncthreads();
    }
    float score = red[0];

    // ---- forward algorithm; renormalize with m = alpha[0] (spread is tiny) ----
    for (int t = 1; t < len; t++) {
        float m = alpha[0];
        p[tid] = (tid < NTAG) ? __expf(alpha[tid] - m) : 0.f;
        __syncthreads();
        float na = 0.f;
        if (tid < NTAG) {
            float sum = 0.f;
            #pragma unroll 4
            for (int i = 0; i < NTAG; i++) sum = fmaf(p[i], E[i * NTAG + tid], sum);
            na = m + __logf(sum) + d_em[(size_t)(t * BATCH + b) * NTAG + tid];
        }
        __syncthreads();
        if (tid < NTAG) alpha[tid] = na;
        __syncthreads();
    }

    float m = alpha[0] + endt[0];
    p[tid] = (tid < NTAG) ? __expf(alpha[tid] + endt[tid] - m) : 0.f;
    __syncthreads();
    for (int s2 = 64; s2 > 0; s2 >>= 1) {
        if (tid < s2) p[tid] += p[tid + s2];
        __syncthreads();
    }
    if (tid == 0) d_llh[b] = score - (m + __logf(p[0]));
}

// ---------------- final reduce: out = -mean(llh) ----------------
__global__ void k_reduce(float* __restrict__ out)
{
    __shared__ float red[256];
    int tid = threadIdx.x;
    red[tid] = d_llh[tid];
    __syncthreads();
    for (int s = 128; s > 0; s >>= 1) {
        if (tid < s) red[tid] += red[tid + s];
        __syncthreads();
    }
    if (tid == 0) out[0] = -red[0] / 256.f;
}

extern "C" void kernel_launch(void* const* d_in, const int* in_sizes, int n_in,
                              void* d_out, int out_size)
{
    const int*   ids   = (const int*)d_in[0];
    const int*   tags  = (const int*)d_in[1];
    const int*   lens  = (const int*)d_in[2];
    const float* embed = (const float*)d_in[3];
    const float* Wihf  = (const float*)d_in[4];
    const float* Whhf  = (const float*)d_in[5];
    const float* bihf  = (const float*)d_in[6];
    const float* bhhf  = (const float*)d_in[7];
    const float* Wihb  = (const float*)d_in[8];
    const float* Whhb  = (const float*)d_in[9];
    const float* bihb  = (const float*)d_in[10];
    const float* bhhb  = (const float*)d_in[11];
    const float* Wout  = (const float*)d_in[12];
    const float* bout  = (const float*)d_in[13];
    const float* start = (const float*)d_in[14];
    const float* endt  = (const float*)d_in[15];
    const float* trans = (const float*)d_in[16];
    const float* h0    = (const float*)d_in[17];
    const float* c0    = (const float*)d_in[18];
    float* out = (float*)d_out;

    cudaFuncSetAttribute(k_recurrent, cudaFuncAttributeMaxDynamicSharedMemorySize, 73728);

    k_init<<<512, 256>>>(h0, c0);
    k_input_gemm<<<dim3(16, 256), 256>>>(ids, embed, Wihf, Wihb, bihf, bhhf, bihb, bhhb);
    k_recurrent<<<RB, 256, 73728>>>(Whhf, Whhb);
    k_emis<<<512, 256>>>(Wout, bout);
    k_crf<<<256, 128>>>(tags, lens, start, endt, trans);
    k_reduce<<<1, 256>>>(out);
}

// round 5
// speedup vs baseline: 1.8555x; 1.4739x over previous
#include <cuda_runtime.h>
#include <cuda_bf16.h>

#define BATCH 256
#define SEQ   128
#define EDIM  512
#define HD    256
#define G4    1024
#define NTAG  76
#define MROWS 32768   // SEQ*BATCH
#define RB    128     // resident blocks in persistent recurrence

// ---------------- scratch (device globals; no runtime allocation) ----------------
__device__ float d_Zf[(size_t)MROWS * G4];   // input proj fwd, (S,B,4HD), gate order i,f,g,o
__device__ float d_Zb[(size_t)MROWS * G4];   // input proj bwd
__device__ float d_HF[(size_t)MROWS * HD];   // fwd hidden history (S,B,HD)
__device__ float d_HB[(size_t)MROWS * HD];   // bwd hidden history (S,B,HD)
__device__ float d_Hping[2 * 2 * BATCH * HD]; // [parity][dir][b][hu]
__device__ float d_C[2 * BATCH * HD];         // [dir][b][hu]
__device__ float d_em[(size_t)MROWS * NTAG];  // emissions (S,B,T)
__device__ float d_llh[BATCH];

__device__ __align__(16) __nv_bfloat16 d_Abf[(size_t)MROWS * EDIM]; // gathered embeddings, bf16
__device__ __align__(16) __nv_bfloat16 d_Wbf[(size_t)2048 * EDIM];  // [Wf;Wb] bf16
__device__ float d_biasZ[2048];                                     // b_ih+b_hh both dirs

__device__ unsigned          d_barCount;
__device__ volatile unsigned d_barPhase;

__device__ __forceinline__ float sigm(float x)  { return 1.0f / (1.0f + __expf(-x)); }
__device__ __forceinline__ float tanh_(float x) { float e = __expf(2.0f * x); return 1.0f - 2.0f / (e + 1.0f); }

// ================= baseline-PTX tensor helpers (no sm_103a-gated instrs) =================
__device__ __forceinline__ unsigned smem_u32(const void* p) {
    unsigned a;
    asm("{ .reg .u64 t; cvta.to.shared.u64 t, %1; cvt.u32.u64 %0, t; }" : "=r"(a) : "l"(p));
    return a;
}
__device__ __forceinline__ void ldsm4(unsigned& r0, unsigned& r1, unsigned& r2, unsigned& r3,
                                      unsigned addr) {
    asm volatile("ldmatrix.sync.aligned.m8n8.x4.shared.b16 {%0,%1,%2,%3}, [%4];"
                 : "=r"(r0), "=r"(r1), "=r"(r2), "=r"(r3) : "r"(addr));
}
__device__ __forceinline__ void mma16816(float* d, const unsigned* a, const unsigned* b) {
    asm volatile(
        "mma.sync.aligned.m16n8k16.row.col.f32.bf16.bf16.f32 "
        "{%0,%1,%2,%3}, {%4,%5,%6,%7}, {%8,%9}, {%0,%1,%2,%3};"
        : "+f"(d[0]), "+f"(d[1]), "+f"(d[2]), "+f"(d[3])
        : "r"(a[0]), "r"(a[1]), "r"(a[2]), "r"(a[3]), "r"(b[0]), "r"(b[1]));
}
__device__ __forceinline__ void cpasync16(unsigned dst, const void* src) {
    asm volatile("cp.async.cg.shared.global [%0], [%1], 16;" :: "r"(dst), "l"(src));
}
#define CP_COMMIT() asm volatile("cp.async.commit_group;" ::: "memory")
#define CP_WAIT(n)  asm volatile("cp.async.wait_group %0;" :: "n"(n) : "memory")

// ---------------- init: h0 -> ping parity 0, c0 -> cell state, reset barrier ----------------
__global__ void k_init(const float* __restrict__ h0, const float* __restrict__ c0)
{
    int i = blockIdx.x * 256 + threadIdx.x;   // grid 512 -> 131072 exact
    d_Hping[i] = h0[i];
    d_C[i]     = c0[i];
    if (i == 0) { d_barCount = 0; d_barPhase = 0; }
}

// ---------------- convert weights + bias: d_Wbf[j] = bf16(W[j]), d_biasZ ----------------
__global__ void k_convW(const float* __restrict__ Wf, const float* __restrict__ Wb,
                        const float* __restrict__ bihf, const float* __restrict__ bhhf,
                        const float* __restrict__ bihb, const float* __restrict__ bhhb)
{
    int j = blockIdx.x;   // 0..2047
    const float* src = (j < 1024) ? (Wf + (size_t)j * EDIM) : (Wb + (size_t)(j - 1024) * EDIM);
    float4 v = ((const float4*)src)[threadIdx.x];   // 128 threads * 4 = 512
    __nv_bfloat162* dst = (__nv_bfloat162*)(d_Wbf + (size_t)j * EDIM);
    dst[threadIdx.x * 2 + 0] = __floats2bfloat162_rn(v.x, v.y);
    dst[threadIdx.x * 2 + 1] = __floats2bfloat162_rn(v.z, v.w);
    if (threadIdx.x == 0)
        d_biasZ[j] = (j < 1024) ? (bihf[j] + bhhf[j]) : (bihb[j - 1024] + bhhb[j - 1024]);
}

// ---------------- gather + convert embeddings: d_Abf[r] = bf16(embed[ids]) ----------------
__global__ void k_gatherA(const int* __restrict__ ids, const float* __restrict__ embed)
{
    int r = blockIdx.x;                                   // 0..32767, r = s*256 + b
    int id = ids[(r & 255) * SEQ + (r >> 8)];             // input_ids[b*S + s]
    float4 v = ((const float4*)(embed + (size_t)id * EDIM))[threadIdx.x];
    __nv_bfloat162* dst = (__nv_bfloat162*)(d_Abf + (size_t)r * EDIM);
    dst[threadIdx.x * 2 + 0] = __floats2bfloat162_rn(v.x, v.y);
    dst[threadIdx.x * 2 + 1] = __floats2bfloat162_rn(v.z, v.w);
}

// ---------------- Z = A @ W^T + bias via mma.sync bf16 ----------------
// grid (16 jtiles, 256 mtiles). CTA: 128x128 tile, 8 warps (4M x 2N), warp 32x64.
// K=512 in 16 chunks of 32, cp.async double-buffered, padded smem (stride 40 bf16).
__global__ void __launch_bounds__(256, 1) k_zmma()
{
    __shared__ __nv_bfloat16 A_s[2][128][40];
    __shared__ __nv_bfloat16 B_s[2][128][40];
    __shared__ float bias_s[128];

    int tid = threadIdx.x;
    int lane = tid & 31, wid = tid >> 5;
    int warp_m = wid >> 1, warp_n = wid & 1;
    int jt = blockIdx.x, mt = blockIdx.y;
    int r0 = mt * 128, j0 = jt * 128;

    if (tid < 128) bias_s[tid] = d_biasZ[j0 + tid];

    unsigned As0 = smem_u32(&A_s[0][0][0]);
    unsigned Bs0 = smem_u32(&B_s[0][0][0]);
    const unsigned BUFB = 128 * 40 * 2;   // bytes per buffer

    // cp.async indices: two 16B chunks per thread per matrix
    int q0 = tid, q1 = tid + 256;
    int rowA0 = q0 >> 2, c0 = (q0 & 3) * 8;     // elem offsets
    int rowA1 = q1 >> 2, c1 = (q1 & 3) * 8;
    unsigned dA0 = (unsigned)(rowA0 * 40 + c0) * 2;
    unsigned dA1 = (unsigned)(rowA1 * 40 + c1) * 2;

    const __nv_bfloat16* Ag = d_Abf + (size_t)r0 * EDIM;
    const __nv_bfloat16* Bg = d_Wbf + (size_t)j0 * EDIM;

    // ldmatrix per-lane element offsets
    unsigned aoff = (unsigned)((warp_m * 32 + (lane & 15)) * 40 + (lane >> 4) * 8);
    unsigned boff = (unsigned)((warp_n * 64 + (lane & 7) + (lane >> 4) * 8) * 40
                               + ((lane >> 3) & 1) * 8);

    float acc[2][8][4];
    #pragma unroll
    for (int mf = 0; mf < 2; mf++)
        #pragma unroll
        for (int j = 0; j < 8; j++)
            #pragma unroll
            for (int q = 0; q < 4; q++) acc[mf][j][q] = 0.f;

    // prefetch stage 0
    {
        cpasync16(As0 + dA0, Ag + (size_t)rowA0 * EDIM + c0);
        cpasync16(As0 + dA1, Ag + (size_t)rowA1 * EDIM + c1);
        cpasync16(Bs0 + dA0, Bg + (size_t)rowA0 * EDIM + c0);
        cpasync16(Bs0 + dA1, Bg + (size_t)rowA1 * EDIM + c1);
        CP_COMMIT();
    }

    for (int kc = 0; kc < 16; kc++) {
        int buf = kc & 1;
        if (kc < 15) {
            int nb = (kc + 1) & 1;
            int ko = (kc + 1) * 32;
            cpasync16(As0 + nb * BUFB + dA0, Ag + (size_t)rowA0 * EDIM + ko + c0);
            cpasync16(As0 + nb * BUFB + dA1, Ag + (size_t)rowA1 * EDIM + ko + c1);
            cpasync16(Bs0 + nb * BUFB + dA0, Bg + (size_t)rowA0 * EDIM + ko + c0);
            cpasync16(Bs0 + nb * BUFB + dA1, Bg + (size_t)rowA1 * EDIM + ko + c1);
            CP_COMMIT();
            CP_WAIT(1);
        } else {
            CP_WAIT(0);
        }
        __syncthreads();

        unsigned Ab = As0 + buf * BUFB;
        unsigned Bb = Bs0 + buf * BUFB;
        #pragma unroll
        for (int kk = 0; kk < 2; kk++) {
            unsigned af[2][4];
            unsigned bfr[4][4];
            #pragma unroll
            for (int f = 0; f < 2; f++)
                ldsm4(af[f][0], af[f][1], af[f][2], af[f][3],
                      Ab + (aoff + f * 640 + kk * 16) * 2);
            #pragma unroll
            for (int g = 0; g < 4; g++)
                ldsm4(bfr[g][0], bfr[g][1], bfr[g][2], bfr[g][3],
                      Bb + (boff + g * 640 + kk * 16) * 2);
            #pragma unroll
            for (int mf = 0; mf < 2; mf++)
                #pragma unroll
                for (int j = 0; j < 8; j++) {
                    unsigned bb[2] = { bfr[j >> 1][(j & 1) * 2], bfr[j >> 1][(j & 1) * 2 + 1] };
                    mma16816(acc[mf][j], af[mf], bb);
                }
        }
        __syncthreads();
    }

    // epilogue: acc + bias -> Z (fwd cols 0..1023, bwd 1024..2047)
    float* Zbase = (j0 < 1024) ? d_Zf : d_Zb;
    int jc0 = (j0 < 1024) ? j0 : (j0 - 1024);
    #pragma unroll
    for (int mf = 0; mf < 2; mf++) {
        int r = r0 + warp_m * 32 + mf * 16 + (lane >> 2);
        #pragma unroll
        for (int j = 0; j < 8; j++) {
            int cl = warp_n * 64 + j * 8 + (lane & 3) * 2;
            float2 v0 = { acc[mf][j][0] + bias_s[cl], acc[mf][j][1] + bias_s[cl + 1] };
            float2 v1 = { acc[mf][j][2] + bias_s[cl], acc[mf][j][3] + bias_s[cl + 1] };
            *(float2*)(Zbase + (size_t)r * G4 + jc0 + cl) = v0;
            *(float2*)(Zbase + (size_t)(r + 8) * G4 + jc0 + cl) = v1;
        }
    }
}

// ---------------- persistent recurrence: all 128 steps, both dirs, 1 launch ----------------
extern __shared__ float smem_dyn[];

__device__ __forceinline__ void grid_barrier(unsigned target)
{
    __syncthreads();
    if (threadIdx.x == 0) {
        __threadfence();
        unsigned arrived = atomicAdd(&d_barCount, 1u) + 1;
        if (arrived == target * RB) {
            __threadfence();
            d_barPhase = target;
        } else {
            while (d_barPhase < target) __nanosleep(64);
            __threadfence();
        }
    }
    __syncthreads();
}

__global__ void __launch_bounds__(256, 1) k_recurrent(
    const float* __restrict__ Whf, const float* __restrict__ Whb)
{
    float* Ws = smem_dyn;            // [256 k][16 hu][4 g]
    float* Hs = smem_dyn + 16384;    // [32 k][64 b]

    int bid = blockIdx.x;
    int dir = bid >> 6;
    int hu0 = ((bid >> 2) & 15) * 16;
    int b0  = (bid & 3) * 64;
    int tid = threadIdx.x;

    const float* Whh = dir ? Whb : Whf;
    const float* Z   = dir ? d_Zb : d_Zf;
    float* Hist      = dir ? d_HB : d_HF;
    float* Cc        = d_C + (size_t)dir * 65536;

    {
        int pair = tid & 63;
        int hu = pair >> 2, g = pair & 3;
        int kq = tid >> 6;
        const float4* src = (const float4*)(Whh + (size_t)(g * 256 + hu0 + hu) * HD + kq * 64);
        #pragma unroll
        for (int i = 0; i < 16; i++) {
            float4 v = src[i];
            int k = kq * 64 + i * 4;
            Ws[(k+0)*64 + hu*4 + g] = v.x;
            Ws[(k+1)*64 + hu*4 + g] = v.y;
            Ws[(k+2)*64 + hu*4 + g] = v.z;
            Ws[(k+3)*64 + hu*4 + g] = v.w;
        }
    }

    int tx = tid & 15, ty = tid >> 4;
    int lrow = tid & 63;
    int lkq  = tid >> 6;

    for (int t = 0; t < SEQ; t++) {
        int s = dir ? (SEQ - 1 - t) : t;
        const float* hprev = d_Hping + (size_t)((t & 1) * 2 + dir) * 65536;
        float*       hnext = d_Hping + (size_t)(((t + 1) & 1) * 2 + dir) * 65536;

        float zv[4][4];
        #pragma unroll
        for (int i = 0; i < 4; i++) {
            int b = b0 + ty * 4 + i;
            const float* zr = Z + (size_t)(s * BATCH + b) * G4 + hu0 + tx;
            zv[i][0] = zr[0];
            zv[i][1] = zr[HD];
            zv[i][2] = zr[2*HD];
            zv[i][3] = zr[3*HD];
        }

        float acc[4][4];
        #pragma unroll
        for (int i = 0; i < 4; i++)
            #pragma unroll
            for (int g = 0; g < 4; g++) acc[i][g] = 0.f;

        for (int k0 = 0; k0 < HD; k0 += 32) {
            float4 h0v = *(const float4*)(hprev + (size_t)(b0 + lrow) * HD + k0 + lkq * 4);
            float4 h1v = *(const float4*)(hprev + (size_t)(b0 + lrow) * HD + k0 + 16 + lkq * 4);
            __syncthreads();
            Hs[(lkq*4+0)*64 + lrow] = h0v.x;
            Hs[(lkq*4+1)*64 + lrow] = h0v.y;
            Hs[(lkq*4+2)*64 + lrow] = h0v.z;
            Hs[(lkq*4+3)*64 + lrow] = h0v.w;
            Hs[(16+lkq*4+0)*64 + lrow] = h1v.x;
            Hs[(16+lkq*4+1)*64 + lrow] = h1v.y;
            Hs[(16+lkq*4+2)*64 + lrow] = h1v.z;
            Hs[(16+lkq*4+3)*64 + lrow] = h1v.w;
            __syncthreads();
            #pragma unroll
            for (int k = 0; k < 32; k++) {
                float4 h4 = *(const float4*)&Hs[k*64 + ty*4];
                float4 w4 = *(const float4*)&Ws[(k0+k)*64 + tx*4];
                float hv[4] = {h4.x, h4.y, h4.z, h4.w};
                float wv[4] = {w4.x, w4.y, w4.z, w4.w};
                #pragma unroll
                for (int i = 0; i < 4; i++)
                    #pragma unroll
                    for (int g = 0; g < 4; g++) acc[i][g] = fmaf(hv[i], wv[g], acc[i][g]);
            }
        }

        int hu = hu0 + tx;
        #pragma unroll
        for (int i = 0; i < 4; i++) {
            int b = b0 + ty * 4 + i;
            float zi = zv[i][0] + acc[i][0];
            float zf = zv[i][1] + acc[i][1];
            float zg = zv[i][2] + acc[i][2];
            float zo = zv[i][3] + acc[i][3];
            size_t ci = (size_t)b * HD + hu;
            float c = sigm(zf) * Cc[ci] + sigm(zi) * tanh_(zg);
            float h = sigm(zo) * tanh_(c);
            Cc[ci] = c;
            hnext[ci] = h;
            Hist[(size_t)(s * BATCH + b) * HD + hu] = h;
        }

        grid_barrier((unsigned)(t + 1));
    }
}

// ---------------- em = [HF|HB] @ W_out^T + b_out ----------------
__global__ void __launch_bounds__(256) k_emis(
    const float* __restrict__ Wout, const float* __restrict__ bout)
{
    __shared__ float As[16][64];
    __shared__ float Bs[16][80];
    int tid = threadIdx.x;
    int r0 = blockIdx.x * 64;
    int tx = tid & 15, ty = tid >> 4;
    float acc[4][5];
    #pragma unroll
    for (int i = 0; i < 4; i++)
        #pragma unroll
        for (int j = 0; j < 5; j++) acc[i][j] = 0.f;

    int lr = tid >> 2, lk = (tid & 3) * 4;
    for (int k0 = 0; k0 < 512; k0 += 16) {
        const float* Abase = (k0 < 256)
            ? (d_HF + (size_t)(r0 + lr) * HD + k0)
            : (d_HB + (size_t)(r0 + lr) * HD + (k0 - 256));
        float4 av = *(const float4*)(Abase + lk);
        As[lk+0][lr] = av.x; As[lk+1][lr] = av.y; As[lk+2][lr] = av.z; As[lk+3][lr] = av.w;
        for (int idx = tid; idx < 80 * 16; idx += 256) {
            int j = idx >> 4, k = idx & 15;
            Bs[k][j] = (j < NTAG) ? Wout[(size_t)j * 512 + k0 + k] : 0.f;
        }
        __syncthreads();
        #pragma unroll
        for (int k = 0; k < 16; k++) {
            float4 a4 = *(const float4*)&As[k][ty * 4];
            float a[4] = {a4.x, a4.y, a4.z, a4.w};
            float bvals[5];
            #pragma unroll
            for (int j = 0; j < 5; j++) bvals[j] = Bs[k][tx * 5 + j];
            #pragma unroll
            for (int i = 0; i < 4; i++)
                #pragma unroll
                for (int j = 0; j < 5; j++) acc[i][j] = fmaf(a[i], bvals[j], acc[i][j]);
        }
        __syncthreads();
    }
    #pragma unroll
    for (int i = 0; i < 4; i++) {
        int r = r0 + ty * 4 + i;
        #pragma unroll
        for (int j = 0; j < 5; j++) {
            int c = tx * 5 + j;
            if (c < NTAG) d_em[(size_t)r * NTAG + c] = acc[i][j] + bout[c];
        }
    }
}

// ---------------- CRF: one block per batch element ----------------
__global__ void __launch_bounds__(128) k_crf(
    const int* __restrict__ tag_ids, const int* __restrict__ lengths,
    const float* __restrict__ start, const float* __restrict__ endt,
    const float* __restrict__ trans)
{
    __shared__ float E[NTAG * NTAG];
    __shared__ float alpha[128];
    __shared__ float p[128];
    __shared__ float red[128];
    int b = blockIdx.x;
    int tid = threadIdx.x;
    int len = lengths[b];

    for (int i = tid; i < NTAG * NTAG; i += 128) E[i] = __expf(trans[i]);

    float part = 0.f;
    if (tid >= 1 && tid < len) {
        int tg = tag_ids[b * SEQ + tid];
        int pv = tag_ids[b * SEQ + tid - 1];
        part = trans[pv * NTAG + tg] + d_em[(size_t)(tid * BATCH + b) * NTAG + tg];
    }
    if (tid == 0) {
        int t0 = tag_ids[b * SEQ];
        part += start[t0] + d_em[(size_t)b * NTAG + t0];
        part += endt[tag_ids[b * SEQ + len - 1]];
    }
    red[tid] = part;
    alpha[tid] = (tid < NTAG) ? start[tid] + d_em[(size_t)b * NTAG + tid] : 0.f;
    __syncthreads();
    for (int s2 = 64; s2 > 0; s2 >>= 1) {
        if (tid < s2) red[tid] += red[tid + s2];
        __syncthreads();
    }
    float score = red[0];

    for (int t = 1; t < len; t++) {
        float m = alpha[0];
        p[tid] = (tid < NTAG) ? __expf(alpha[tid] - m) : 0.f;
        __syncthreads();
        float na = 0.f;
        if (tid < NTAG) {
            float sum = 0.f;
            #pragma unroll 4
            for (int i = 0; i < NTAG; i++) sum = fmaf(p[i], E[i * NTAG + tid], sum);
            na = m + __logf(sum) + d_em[(size_t)(t * BATCH + b) * NTAG + tid];
        }
        __syncthreads();
        if (tid < NTAG) alpha[tid] = na;
        __syncthreads();
    }

    float m = alpha[0] + endt[0];
    p[tid] = (tid < NTAG) ? __expf(alpha[tid] + endt[tid] - m) : 0.f;
    __syncthreads();
    for (int s2 = 64; s2 > 0; s2 >>= 1) {
        if (tid < s2) p[tid] += p[tid + s2];
        __syncthreads();
    }
    if (tid == 0) d_llh[b] = score - (m + __logf(p[0]));
}

// ---------------- final reduce: out = -mean(llh) ----------------
__global__ void k_reduce(float* __restrict__ out)
{
    __shared__ float red[256];
    int tid = threadIdx.x;
    red[tid] = d_llh[tid];
    __syncthreads();
    for (int s = 128; s > 0; s >>= 1) {
        if (tid < s) red[tid] += red[tid + s];
        __syncthreads();
    }
    if (tid == 0) out[0] = -red[0] / 256.f;
}

extern "C" void kernel_launch(void* const* d_in, const int* in_sizes, int n_in,
                              void* d_out, int out_size)
{
    const int*   ids   = (const int*)d_in[0];
    const int*   tags  = (const int*)d_in[1];
    const int*   lens  = (const int*)d_in[2];
    const float* embed = (const float*)d_in[3];
    const float* Wihf  = (const float*)d_in[4];
    const float* Whhf  = (const float*)d_in[5];
    const float* bihf  = (const float*)d_in[6];
    const float* bhhf  = (const float*)d_in[7];
    const float* Wihb  = (const float*)d_in[8];
    const float* Whhb  = (const float*)d_in[9];
    const float* bihb  = (const float*)d_in[10];
    const float* bhhb  = (const float*)d_in[11];
    const float* Wout  = (const float*)d_in[12];
    const float* bout  = (const float*)d_in[13];
    const float* start = (const float*)d_in[14];
    const float* endt  = (const float*)d_in[15];
    const float* trans = (const float*)d_in[16];
    const float* h0    = (const float*)d_in[17];
    const float* c0    = (const float*)d_in[18];
    float* out = (float*)d_out;

    cudaFuncSetAttribute(k_recurrent, cudaFuncAttributeMaxDynamicSharedMemorySize, 73728);

    k_init<<<512, 256>>>(h0, c0);
    k_convW<<<2048, 128>>>(Wihf, Wihb, bihf, bhhf, bihb, bhhb);
    k_gatherA<<<MROWS, 128>>>(ids, embed);
    k_zmma<<<dim3(16, 256), 256>>>();
    k_recurrent<<<RB, 256, 73728>>>(Whhf, Whhb);
    k_emis<<<512, 256>>>(Wout, bout);
    k_crf<<<256, 128>>>(tags, lens, start, endt, trans);
    k_reduce<<<1, 256>>>(out);
}

// round 6
// speedup vs baseline: 3.2940x; 1.7752x over previous
#include <cuda_runtime.h>
#include <cuda_bf16.h>

#define BATCH 256
#define SEQ   128
#define EDIM  512
#define HD    256
#define G4    1024
#define NTAG  76
#define MROWS 32768   // SEQ*BATCH
#define RB    128     // resident blocks in persistent recurrence
#define WST   264     // smem row stride (bf16 elems) for ldmatrix, conflict-free

// ---------------- scratch (device globals; no runtime allocation) ----------------
__device__ float d_Zf[(size_t)MROWS * G4];   // input proj fwd, (S,B,4HD), gate order i,f,g,o
__device__ float d_Zb[(size_t)MROWS * G4];   // input proj bwd
__device__ float d_HF[(size_t)MROWS * HD];   // fwd hidden history (S,B,HD)
__device__ float d_HB[(size_t)MROWS * HD];   // bwd hidden history (S,B,HD)
__device__ float d_em[(size_t)MROWS * NTAG]; // emissions (S,B,T)
__device__ float d_llh[BATCH];

__device__ __align__(16) __nv_bfloat16 d_Hbf[2 * 2 * BATCH * HD];  // [parity][dir][b][hu]
__device__ __align__(16) __nv_bfloat16 d_Abf[(size_t)MROWS * EDIM]; // gathered embeddings, bf16
__device__ __align__(16) __nv_bfloat16 d_Wbf[(size_t)2048 * EDIM];  // [Wf;Wb] bf16
__device__ float d_biasZ[2048];                                     // b_ih+b_hh both dirs

__device__ unsigned          d_barCount;
__device__ volatile unsigned d_barPhase;

__device__ __forceinline__ float sigm(float x)  { return 1.0f / (1.0f + __expf(-x)); }
__device__ __forceinline__ float tanh_(float x) { float e = __expf(2.0f * x); return 1.0f - 2.0f / (e + 1.0f); }

// ================= baseline-PTX tensor helpers (no sm_103a-gated instrs) =================
__device__ __forceinline__ unsigned smem_u32(const void* p) {
    unsigned a;
    asm("{ .reg .u64 t; cvta.to.shared.u64 t, %1; cvt.u32.u64 %0, t; }" : "=r"(a) : "l"(p));
    return a;
}
__device__ __forceinline__ void ldsm4(unsigned& r0, unsigned& r1, unsigned& r2, unsigned& r3,
                                      unsigned addr) {
    asm volatile("ldmatrix.sync.aligned.m8n8.x4.shared.b16 {%0,%1,%2,%3}, [%4];"
                 : "=r"(r0), "=r"(r1), "=r"(r2), "=r"(r3) : "r"(addr));
}
__device__ __forceinline__ void mma16816(float* d, const unsigned* a, const unsigned* b) {
    asm volatile(
        "mma.sync.aligned.m16n8k16.row.col.f32.bf16.bf16.f32 "
        "{%0,%1,%2,%3}, {%4,%5,%6,%7}, {%8,%9}, {%0,%1,%2,%3};"
        : "+f"(d[0]), "+f"(d[1]), "+f"(d[2]), "+f"(d[3])
        : "r"(a[0]), "r"(a[1]), "r"(a[2]), "r"(a[3]), "r"(b[0]), "r"(b[1]));
}
__device__ __forceinline__ void cpasync16(unsigned dst, const void* src) {
    asm volatile("cp.async.cg.shared.global [%0], [%1], 16;" :: "r"(dst), "l"(src));
}
#define CP_COMMIT() asm volatile("cp.async.commit_group;" ::: "memory")
#define CP_WAIT(n)  asm volatile("cp.async.wait_group %0;" :: "n"(n) : "memory")

// ---------------- init: h0 -> bf16 ping parity 0, reset barrier ----------------
__global__ void k_init(const float* __restrict__ h0)
{
    int i = blockIdx.x * 256 + threadIdx.x;   // grid 512 -> 131072 exact
    d_Hbf[i] = __float2bfloat16(h0[i]);
    if (i == 0) { d_barCount = 0; d_barPhase = 0; }
}

// ---------------- convert weights + bias: d_Wbf[j] = bf16(W[j]), d_biasZ ----------------
__global__ void k_convW(const float* __restrict__ Wf, const float* __restrict__ Wb,
                        const float* __restrict__ bihf, const float* __restrict__ bhhf,
                        const float* __restrict__ bihb, const float* __restrict__ bhhb)
{
    int j = blockIdx.x;   // 0..2047
    const float* src = (j < 1024) ? (Wf + (size_t)j * EDIM) : (Wb + (size_t)(j - 1024) * EDIM);
    float4 v = ((const float4*)src)[threadIdx.x];   // 128 threads * 4 = 512
    __nv_bfloat162* dst = (__nv_bfloat162*)(d_Wbf + (size_t)j * EDIM);
    dst[threadIdx.x * 2 + 0] = __floats2bfloat162_rn(v.x, v.y);
    dst[threadIdx.x * 2 + 1] = __floats2bfloat162_rn(v.z, v.w);
    if (threadIdx.x == 0)
        d_biasZ[j] = (j < 1024) ? (bihf[j] + bhhf[j]) : (bihb[j - 1024] + bhhb[j - 1024]);
}

// ---------------- gather + convert embeddings: d_Abf[r] = bf16(embed[ids]) ----------------
__global__ void k_gatherA(const int* __restrict__ ids, const float* __restrict__ embed)
{
    int r = blockIdx.x;                                   // 0..32767, r = s*256 + b
    int id = ids[(r & 255) * SEQ + (r >> 8)];             // input_ids[b*S + s]
    float4 v = ((const float4*)(embed + (size_t)id * EDIM))[threadIdx.x];
    __nv_bfloat162* dst = (__nv_bfloat162*)(d_Abf + (size_t)r * EDIM);
    dst[threadIdx.x * 2 + 0] = __floats2bfloat162_rn(v.x, v.y);
    dst[threadIdx.x * 2 + 1] = __floats2bfloat162_rn(v.z, v.w);
}

// ---------------- Z = A @ W^T + bias via mma.sync bf16 ----------------
// grid (16 jtiles, 256 mtiles). CTA: 128x128 tile, 8 warps (4M x 2N), warp 32x64.
__global__ void __launch_bounds__(256, 1) k_zmma()
{
    __shared__ __nv_bfloat16 A_s[2][128][40];
    __shared__ __nv_bfloat16 B_s[2][128][40];
    __shared__ float bias_s[128];

    int tid = threadIdx.x;
    int lane = tid & 31, wid = tid >> 5;
    int warp_m = wid >> 1, warp_n = wid & 1;
    int jt = blockIdx.x, mt = blockIdx.y;
    int r0 = mt * 128, j0 = jt * 128;

    if (tid < 128) bias_s[tid] = d_biasZ[j0 + tid];

    unsigned As0 = smem_u32(&A_s[0][0][0]);
    unsigned Bs0 = smem_u32(&B_s[0][0][0]);
    const unsigned BUFB = 128 * 40 * 2;   // bytes per buffer

    int q0 = tid, q1 = tid + 256;
    int rowA0 = q0 >> 2, c0 = (q0 & 3) * 8;
    int rowA1 = q1 >> 2, c1 = (q1 & 3) * 8;
    unsigned dA0 = (unsigned)(rowA0 * 40 + c0) * 2;
    unsigned dA1 = (unsigned)(rowA1 * 40 + c1) * 2;

    const __nv_bfloat16* Ag = d_Abf + (size_t)r0 * EDIM;
    const __nv_bfloat16* Bg = d_Wbf + (size_t)j0 * EDIM;

    unsigned aoff = (unsigned)((warp_m * 32 + (lane & 15)) * 40 + (lane >> 4) * 8);
    unsigned boff = (unsigned)((warp_n * 64 + (lane & 7) + (lane >> 4) * 8) * 40
                               + ((lane >> 3) & 1) * 8);

    float acc[2][8][4];
    #pragma unroll
    for (int mf = 0; mf < 2; mf++)
        #pragma unroll
        for (int j = 0; j < 8; j++)
            #pragma unroll
            for (int q = 0; q < 4; q++) acc[mf][j][q] = 0.f;

    {
        cpasync16(As0 + dA0, Ag + (size_t)rowA0 * EDIM + c0);
        cpasync16(As0 + dA1, Ag + (size_t)rowA1 * EDIM + c1);
        cpasync16(Bs0 + dA0, Bg + (size_t)rowA0 * EDIM + c0);
        cpasync16(Bs0 + dA1, Bg + (size_t)rowA1 * EDIM + c1);
        CP_COMMIT();
    }

    for (int kc = 0; kc < 16; kc++) {
        int buf = kc & 1;
        if (kc < 15) {
            int nb = (kc + 1) & 1;
            int ko = (kc + 1) * 32;
            cpasync16(As0 + nb * BUFB + dA0, Ag + (size_t)rowA0 * EDIM + ko + c0);
            cpasync16(As0 + nb * BUFB + dA1, Ag + (size_t)rowA1 * EDIM + ko + c1);
            cpasync16(Bs0 + nb * BUFB + dA0, Bg + (size_t)rowA0 * EDIM + ko + c0);
            cpasync16(Bs0 + nb * BUFB + dA1, Bg + (size_t)rowA1 * EDIM + ko + c1);
            CP_COMMIT();
            CP_WAIT(1);
        } else {
            CP_WAIT(0);
        }
        __syncthreads();

        unsigned Ab = As0 + buf * BUFB;
        unsigned Bb = Bs0 + buf * BUFB;
        #pragma unroll
        for (int kk = 0; kk < 2; kk++) {
            unsigned af[2][4];
            unsigned bfr[4][4];
            #pragma unroll
            for (int f = 0; f < 2; f++)
                ldsm4(af[f][0], af[f][1], af[f][2], af[f][3],
                      Ab + (aoff + f * 640 + kk * 16) * 2);
            #pragma unroll
            for (int g = 0; g < 4; g++)
                ldsm4(bfr[g][0], bfr[g][1], bfr[g][2], bfr[g][3],
                      Bb + (boff + g * 640 + kk * 16) * 2);
            #pragma unroll
            for (int mf = 0; mf < 2; mf++)
                #pragma unroll
                for (int j = 0; j < 8; j++) {
                    unsigned bb[2] = { bfr[j >> 1][(j & 1) * 2], bfr[j >> 1][(j & 1) * 2 + 1] };
                    mma16816(acc[mf][j], af[mf], bb);
                }
        }
        __syncthreads();
    }

    float* Zbase = (j0 < 1024) ? d_Zf : d_Zb;
    int jc0 = (j0 < 1024) ? j0 : (j0 - 1024);
    #pragma unroll
    for (int mf = 0; mf < 2; mf++) {
        int r = r0 + warp_m * 32 + mf * 16 + (lane >> 2);
        #pragma unroll
        for (int j = 0; j < 8; j++) {
            int cl = warp_n * 64 + j * 8 + (lane & 3) * 2;
            float2 v0 = { acc[mf][j][0] + bias_s[cl], acc[mf][j][1] + bias_s[cl + 1] };
            float2 v1 = { acc[mf][j][2] + bias_s[cl], acc[mf][j][3] + bias_s[cl + 1] };
            *(float2*)(Zbase + (size_t)r * G4 + jc0 + cl) = v0;
            *(float2*)(Zbase + (size_t)(r + 8) * G4 + jc0 + cl) = v1;
        }
    }
}

// ---------------- persistent tensor-core recurrence ----------------
// 128 blocks x 128 threads (4 warps). Block = (dir, 16-hu tile, 64-batch tile).
// Whh slice bf16 in smem once (cols j = g*16+hu, k contiguous). h ping-pong in
// bf16 global, cp.async'd to smem each step. Cell state c lives in registers.
extern __shared__ __nv_bfloat16 sm_rec[];

__device__ __forceinline__ void grid_barrier(unsigned target)
{
    __syncthreads();
    if (threadIdx.x == 0) {
        __threadfence();
        unsigned arrived = atomicAdd(&d_barCount, 1u) + 1;
        if (arrived == target * RB) {
            __threadfence();
            d_barPhase = target;
        } else {
            while (d_barPhase < target) __nanosleep(64);
            __threadfence();
        }
    }
    __syncthreads();
}

__global__ void __launch_bounds__(128, 1) k_recurrent(
    const float* __restrict__ Whf, const float* __restrict__ Whb,
    const float* __restrict__ c0)
{
    __nv_bfloat16* Wsb = sm_rec;              // [64 j][WST]
    __nv_bfloat16* Hsm = sm_rec + 64 * WST;   // [64 b][WST]

    int bid = blockIdx.x;
    int dir = bid >> 6;
    int hu0 = ((bid >> 2) & 15) * 16;
    int b0  = (bid & 3) * 64;
    int tid = threadIdx.x;
    int lane = tid & 31, warp = tid >> 5;

    const float* Whh = dir ? Whb : Whf;
    const float* Z   = dir ? d_Zb : d_Zf;
    float* Hist      = dir ? d_HB : d_HF;

    // ---- load + convert W slice once: Wsb[j][k], j = g*16 + hu_local ----
    {
        int j = tid >> 1;                       // 0..63
        int kh = (tid & 1) * 128;               // k half
        int g = j >> 4, hul = j & 15;
        const float4* src = (const float4*)(Whh + (size_t)(g * 256 + hu0 + hul) * HD + kh);
        __nv_bfloat162* dst = (__nv_bfloat162*)(Wsb + j * WST + kh);
        #pragma unroll
        for (int q = 0; q < 32; q++) {
            float4 v = src[q];
            dst[q * 2 + 0] = __floats2bfloat162_rn(v.x, v.y);
            dst[q * 2 + 1] = __floats2bfloat162_rn(v.z, v.w);
        }
    }

    // thread cell mapping: rows b = b0 + warp*16 + (lane>>2) + rs*8,
    // cols hu = hu0 + hh*8 + (lane&3)*2 + hp, gate g in acc[g*2+hh][rs*2+hp]
    int bbase = b0 + warp * 16 + (lane >> 2);
    int hbase = (lane & 3) * 2;

    float creg[2][2][2];
    #pragma unroll
    for (int rs = 0; rs < 2; rs++)
        #pragma unroll
        for (int hh = 0; hh < 2; hh++) {
            float2 cv = *(const float2*)(c0 + (size_t)dir * 65536
                          + (size_t)(bbase + rs * 8) * HD + hu0 + hh * 8 + hbase);
            creg[rs][hh][0] = cv.x;
            creg[rs][hh][1] = cv.y;
        }

    unsigned HsmB = smem_u32(Hsm);
    unsigned WsbB = smem_u32(Wsb);
    unsigned aoff = HsmB + ((warp * 16 + (lane & 15)) * WST + (lane >> 4) * 8) * 2;
    unsigned boff = WsbB + (((lane & 7) + (lane >> 4) * 8) * WST + ((lane >> 3) & 1) * 8) * 2;

    __syncthreads();

    for (int t = 0; t < SEQ; t++) {
        int s = dir ? (SEQ - 1 - t) : t;
        const __nv_bfloat16* hsrc = d_Hbf + (size_t)((t & 1) * 2 + dir) * 65536;
        __nv_bfloat16*       hdst = d_Hbf + (size_t)(((t + 1) & 1) * 2 + dir) * 65536;

        // cp.async h_prev tile (64 rows x 256 k bf16)
        #pragma unroll
        for (int i = 0; i < 16; i++) {
            int ch = tid + i * 128;
            int row = ch >> 5, ko = (ch & 31) * 8;
            cpasync16(HsmB + (unsigned)(row * WST + ko) * 2,
                      hsrc + (size_t)(b0 + row) * HD + ko);
        }
        CP_COMMIT();

        // Z gate biases (independent of the GEMM; overlap with cp.async)
        float zr[2][2][4][2];
        #pragma unroll
        for (int rs = 0; rs < 2; rs++) {
            const float* zp = Z + (size_t)(s * BATCH + bbase + rs * 8) * G4;
            #pragma unroll
            for (int hh = 0; hh < 2; hh++) {
                int hu = hu0 + hh * 8 + hbase;
                #pragma unroll
                for (int g = 0; g < 4; g++) {
                    float2 v = *(const float2*)(zp + g * 256 + hu);
                    zr[rs][hh][g][0] = v.x;
                    zr[rs][hh][g][1] = v.y;
                }
            }
        }

        CP_WAIT(0);
        __syncthreads();

        float acc[8][4];
        #pragma unroll
        for (int f = 0; f < 8; f++)
            #pragma unroll
            for (int q = 0; q < 4; q++) acc[f][q] = 0.f;

        #pragma unroll
        for (int kk = 0; kk < 16; kk++) {
            unsigned a[4];
            ldsm4(a[0], a[1], a[2], a[3], aoff + kk * 32);
            unsigned bq[4][4];
            #pragma unroll
            for (int g2 = 0; g2 < 4; g2++)
                ldsm4(bq[g2][0], bq[g2][1], bq[g2][2], bq[g2][3],
                      boff + g2 * (16 * WST * 2) + kk * 32);
            #pragma unroll
            for (int f = 0; f < 8; f++) {
                unsigned bb[2] = { bq[f >> 1][(f & 1) * 2], bq[f >> 1][(f & 1) * 2 + 1] };
                mma16816(acc[f], a, bb);
            }
        }

        // gates + cell update, all in registers
        #pragma unroll
        for (int rs = 0; rs < 2; rs++) {
            int b = bbase + rs * 8;
            #pragma unroll
            for (int hh = 0; hh < 2; hh++) {
                int hu = hu0 + hh * 8 + hbase;
                float2 hf;
                #pragma unroll
                for (int hp = 0; hp < 2; hp++) {
                    float zi = zr[rs][hh][0][hp] + acc[0 + hh][rs * 2 + hp];
                    float zf = zr[rs][hh][1][hp] + acc[2 + hh][rs * 2 + hp];
                    float zg = zr[rs][hh][2][hp] + acc[4 + hh][rs * 2 + hp];
                    float zo = zr[rs][hh][3][hp] + acc[6 + hh][rs * 2 + hp];
                    float cv = sigm(zf) * creg[rs][hh][hp] + sigm(zi) * tanh_(zg);
                    float h  = sigm(zo) * tanh_(cv);
                    creg[rs][hh][hp] = cv;
                    if (hp) hf.y = h; else hf.x = h;
                }
                *(float2*)(Hist + (size_t)(s * BATCH + b) * HD + hu) = hf;
                *(__nv_bfloat162*)(hdst + (size_t)b * HD + hu) =
                    __floats2bfloat162_rn(hf.x, hf.y);
            }
        }

        grid_barrier((unsigned)(t + 1));
    }
}

// ---------------- em = [HF|HB] @ W_out^T + b_out ----------------
__global__ void __launch_bounds__(256) k_emis(
    const float* __restrict__ Wout, const float* __restrict__ bout)
{
    __shared__ float As[16][64];
    __shared__ float Bs[16][80];
    int tid = threadIdx.x;
    int r0 = blockIdx.x * 64;
    int tx = tid & 15, ty = tid >> 4;
    float acc[4][5];
    #pragma unroll
    for (int i = 0; i < 4; i++)
        #pragma unroll
        for (int j = 0; j < 5; j++) acc[i][j] = 0.f;

    int lr = tid >> 2, lk = (tid & 3) * 4;
    for (int k0 = 0; k0 < 512; k0 += 16) {
        const float* Abase = (k0 < 256)
            ? (d_HF + (size_t)(r0 + lr) * HD + k0)
            : (d_HB + (size_t)(r0 + lr) * HD + (k0 - 256));
        float4 av = *(const float4*)(Abase + lk);
        As[lk+0][lr] = av.x; As[lk+1][lr] = av.y; As[lk+2][lr] = av.z; As[lk+3][lr] = av.w;
        for (int idx = tid; idx < 80 * 16; idx += 256) {
            int j = idx >> 4, k = idx & 15;
            Bs[k][j] = (j < NTAG) ? Wout[(size_t)j * 512 + k0 + k] : 0.f;
        }
        __syncthreads();
        #pragma unroll
        for (int k = 0; k < 16; k++) {
            float4 a4 = *(const float4*)&As[k][ty * 4];
            float a[4] = {a4.x, a4.y, a4.z, a4.w};
            float bvals[5];
            #pragma unroll
            for (int j = 0; j < 5; j++) bvals[j] = Bs[k][tx * 5 + j];
            #pragma unroll
            for (int i = 0; i < 4; i++)
                #pragma unroll
                for (int j = 0; j < 5; j++) acc[i][j] = fmaf(a[i], bvals[j], acc[i][j]);
        }
        __syncthreads();
    }
    #pragma unroll
    for (int i = 0; i < 4; i++) {
        int r = r0 + ty * 4 + i;
        #pragma unroll
        for (int j = 0; j < 5; j++) {
            int c = tx * 5 + j;
            if (c < NTAG) d_em[(size_t)r * NTAG + c] = acc[i][j] + bout[c];
        }
    }
}

// ---------------- CRF: one block per batch element ----------------
__global__ void __launch_bounds__(128) k_crf(
    const int* __restrict__ tag_ids, const int* __restrict__ lengths,
    const float* __restrict__ start, const float* __restrict__ endt,
    const float* __restrict__ trans)
{
    __shared__ float E[NTAG * NTAG];
    __shared__ float alpha[128];
    __shared__ float p[128];
    __shared__ float red[128];
    int b = blockIdx.x;
    int tid = threadIdx.x;
    int len = lengths[b];

    for (int i = tid; i < NTAG * NTAG; i += 128) E[i] = __expf(trans[i]);

    float part = 0.f;
    if (tid >= 1 && tid < len) {
        int tg = tag_ids[b * SEQ + tid];
        int pv = tag_ids[b * SEQ + tid - 1];
        part = trans[pv * NTAG + tg] + d_em[(size_t)(tid * BATCH + b) * NTAG + tg];
    }
    if (tid == 0) {
        int t0 = tag_ids[b * SEQ];
        part += start[t0] + d_em[(size_t)b * NTAG + t0];
        part += endt[tag_ids[b * SEQ + len - 1]];
    }
    red[tid] = part;
    alpha[tid] = (tid < NTAG) ? start[tid] + d_em[(size_t)b * NTAG + tid] : 0.f;
    __syncthreads();
    for (int s2 = 64; s2 > 0; s2 >>= 1) {
        if (tid < s2) red[tid] += red[tid + s2];
        __syncthreads();
    }
    float score = red[0];

    for (int t = 1; t < len; t++) {
        float m = alpha[0];
        p[tid] = (tid < NTAG) ? __expf(alpha[tid] - m) : 0.f;
        __syncthreads();
        float na = 0.f;
        if (tid < NTAG) {
            float sum = 0.f;
            #pragma unroll 4
            for (int i = 0; i < NTAG; i++) sum = fmaf(p[i], E[i * NTAG + tid], sum);
            na = m + __logf(sum) + d_em[(size_t)(t * BATCH + b) * NTAG + tid];
        }
        __syncthreads();
        if (tid < NTAG) alpha[tid] = na;
        __syncthreads();
    }

    float m = alpha[0] + endt[0];
    p[tid] = (tid < NTAG) ? __expf(alpha[tid] + endt[tid] - m) : 0.f;
    __syncthreads();
    for (int s2 = 64; s2 > 0; s2 >>= 1) {
        if (tid < s2) p[tid] += p[tid + s2];
        __syncthreads();
    }
    if (tid == 0) d_llh[b] = score - (m + __logf(p[0]));
}

// ---------------- final reduce: out = -mean(llh) ----------------
__global__ void k_reduce(float* __restrict__ out)
{
    __shared__ float red[256];
    int tid = threadIdx.x;
    red[tid] = d_llh[tid];
    __syncthreads();
    for (int s = 128; s > 0; s >>= 1) {
        if (tid < s) red[tid] += red[tid + s];
        __syncthreads();
    }
    if (tid == 0) out[0] = -red[0] / 256.f;
}

extern "C" void kernel_launch(void* const* d_in, const int* in_sizes, int n_in,
                              void* d_out, int out_size)
{
    const int*   ids   = (const int*)d_in[0];
    const int*   tags  = (const int*)d_in[1];
    const int*   lens  = (const int*)d_in[2];
    const float* embed = (const float*)d_in[3];
    const float* Wihf  = (const float*)d_in[4];
    const float* Whhf  = (const float*)d_in[5];
    const float* bihf  = (const float*)d_in[6];
    const float* bhhf  = (const float*)d_in[7];
    const float* Wihb  = (const float*)d_in[8];
    const float* Whhb  = (const float*)d_in[9];
    const float* bihb  = (const float*)d_in[10];
    const float* bhhb  = (const float*)d_in[11];
    const float* Wout  = (const float*)d_in[12];
    const float* bout  = (const float*)d_in[13];
    const float* start = (const float*)d_in[14];
    const float* endt  = (const float*)d_in[15];
    const float* trans = (const float*)d_in[16];
    const float* h0    = (const float*)d_in[17];
    const float* c0    = (const float*)d_in[18];
    float* out = (float*)d_out;

    const int RSMEM = 2 * 64 * WST * 2;   // Wsb + Hsm, bf16
    cudaFuncSetAttribute(k_recurrent, cudaFuncAttributeMaxDynamicSharedMemorySize, RSMEM);

    k_init<<<512, 256>>>(h0);
    k_convW<<<2048, 128>>>(Wihf, Wihb, bihf, bhhf, bihb, bhhb);
    k_gatherA<<<MROWS, 128>>>(ids, embed);
    k_zmma<<<dim3(16, 256), 256>>>();
    k_recurrent<<<RB, 128, RSMEM>>>(Whhf, Whhb, c0);
    k_emis<<<512, 256>>>(Wout, bout);
    k_crf<<<256, 128>>>(tags, lens, start, endt, trans);
    k_reduce<<<1, 256>>>(out);
}